// round 15
// baseline (speedup 1.0000x reference)
#include <cuda_runtime.h>
#include <cstdint>

// ---------------------------------------------------------------------------
// SNN multi-layer LIF with feedback. B=512, D=2048, L=3, T=16.
// Bitwise-exact fp32, chunk-512 blocked-K accumulation (verified R4/R5).
// Round 15: R12 mainloop (best GEMM: 5583us total) + reduce+LIF epilogue
// fused via an all-CTA grid barrier: all 256 CTAs (co-resident: 2 CTAs/SM,
// 296 slots) arrive on a phase-counter barrier, then each folds 1/256 of the
// partials in the SAME ascending order as the standalone reduce kernel.
// 48 launches total (was 96). Per-element math bitwise identical.
// ---------------------------------------------------------------------------

#define Bsz 512
#define Dd  2048
#define NL  3
#define TSTEPS 16
#define DD (Dd * Dd)
#define BD (Bsz * Dd)
#define NCHUNK 4
#define KCHUNK 512
#define GRID_CTAS 256

__device__ float g_x1[BD];
__device__ float g_u[NL][BD];
__device__ float g_s[NL][BD];
__device__ float g_af[BD];
__device__ float g_al[BD];
__device__ float g_part[NCHUNK][BD];
__device__ int   g_bar_cnt;      // zero-init; returns to 0 every stage
__device__ int   g_bar_phase;    // monotonic

#define VTH 1.0f
#define LK  0.9f
// (1 - 0.9^16) / (1 - 0.9) rounded to f32
#define WEIGHTED 8.146979811148159f

__device__ __forceinline__ uint64_t ffma2(uint64_t a, uint64_t b, uint64_t c) {
    uint64_t d;
    asm("fma.rn.f32x2 %0, %1, %2, %3;" : "=l"(d) : "l"(a), "l"(b), "l"(c));
    return d;
}
__device__ __forceinline__ void lds_pair(uint32_t addr, uint64_t& p0, uint64_t& p1) {
    asm volatile("ld.shared.v2.b64 {%0, %1}, [%2];" : "=l"(p0), "=l"(p1) : "r"(addr));
}
__device__ __forceinline__ void unpack2(uint64_t p, float& lo, float& hi) {
    asm("mov.b64 {%0, %1}, %2;" : "=f"(lo), "=f"(hi) : "l"(p));
}
__device__ __forceinline__ void cp16(uint32_t s, const void* g) {
    asm volatile("cp.async.ca.shared.global [%0], [%1], 16;" :: "r"(s), "l"(g));
}
#define CP_COMMIT() asm volatile("cp.async.commit_group;")
#define CP_WAIT0()  asm volatile("cp.async.wait_group 0;")

// ---------------------------------------------------------------------------
// Fused GEMM-chunk + grid barrier + distributed reduce+LIF epilogue.
// BM=BN=128, BK=16, 256 threads, 8x8 micro-tile via packed f32x2 FMA.
// Thread n-columns: {4tx..4tx+3} and {64+4tx..64+4tx+3} (conflict-free B).
// ---------------------------------------------------------------------------
template<bool ADD_UPREV, bool ADD_X1, bool WRITE_RAW, int ACCM>
__global__ __launch_bounds__(256, 2)
void gemm_lif_fused(const float* __restrict__ Aext,
                    const float* __restrict__ W,
                    const float* __restrict__ bias,
                    int a_sel, int layer,
                    float* __restrict__ finout)
{
    const float* __restrict__ A = (a_sel < 0) ? Aext : g_s[a_sel];

    // As2: A stored duplicated: As2[k][2m] = As2[k][2m+1] = A[m][k]
    __shared__ float As2[2][16][256];   // 32 KB
    __shared__ float Bs[2][16][128];    // 16 KB (48 KB total)

    const int tid = threadIdx.x;
    const int bn0 = blockIdx.x * 128;
    const int bm0 = blockIdx.y * 128;
    const int k0  = blockIdx.z * KCHUNK;

    // A loader: 128 rows x 16 k; 2 float4 per thread
    const int ar = tid >> 1;            // 0..127
    const int ac = (tid & 1) << 3;      // 0 or 8
    // B loader: 16 k-rows x 128 n; 2 x 16B cp.async per thread
    const int wr = tid >> 4;            // 0..15
    const int wc = (tid & 15) << 3;     // 0..120

    const float* __restrict__ Ap = A + (size_t)(bm0 + ar) * Dd + (k0 + ac);
    const float* __restrict__ Wp = W + (size_t)(k0 + wr) * Dd + (bn0 + wc);

    const uint32_t sBw0 = (uint32_t)__cvta_generic_to_shared(&Bs[0][wr][wc]);
    const uint32_t sBw1 = sBw0 + 16;
    const uint32_t B_BUF = 16 * 128 * 4;

    // prime buffer 0
    {
        cp16(sBw0, Wp);
        cp16(sBw1, Wp + 4);
        CP_COMMIT();
        float4 a0 = *(const float4*)Ap;
        float4 a1 = *(const float4*)(Ap + 4);
        float av[8] = {a0.x, a0.y, a0.z, a0.w, a1.x, a1.y, a1.z, a1.w};
        #pragma unroll
        for (int i = 0; i < 8; ++i)
            *(float2*)&As2[0][ac + i][2 * ar] = make_float2(av[i], av[i]);
        CP_WAIT0();
    }
    __syncthreads();

    const int tx = tid & 15;            // n group
    const int ty = tid >> 4;            // m group
    const int rm = ty << 3;             // 0..120

    const uint32_t sA = (uint32_t)__cvta_generic_to_shared(&As2[0][0][0]) + rm * 8;
    // B: this thread reads 16B at column 4*tx and 16B at column 64+4*tx.
    const uint32_t sB = (uint32_t)__cvta_generic_to_shared(&Bs[0][0][0])  + tx * 16;
    const uint32_t A_BUF = 16 * 256 * 4;

    uint64_t acc[8][4];
    #pragma unroll
    for (int i = 0; i < 8; ++i)
        #pragma unroll
        for (int j = 0; j < 4; ++j) acc[i][j] = 0ull;

    const int NT = KCHUNK / 16;         // 32 K-tiles
    #pragma unroll 1
    for (int t = 0; t < NT; ++t) {
        const int cur = t & 1;
        const bool more = (t + 1 < NT);

        float4 a0, a1;
        if (more) {
            const int nb = (t + 1) & 1;
            const float* Wp2 = Wp + (size_t)(t + 1) * 16 * Dd;
            cp16(sBw0 + nb * B_BUF, Wp2);
            cp16(sBw1 + nb * B_BUF, Wp2 + 4);
            CP_COMMIT();
            const float* Ap2 = Ap + (t + 1) * 16;
            a0 = *(const float4*)Ap2;
            a1 = *(const float4*)(Ap2 + 4);
        }

        const uint32_t baseA = sA + cur * A_BUF;
        const uint32_t baseB = sB + cur * B_BUF;

        #pragma unroll
        for (int kk = 0; kk < 16; ++kk) {
            uint64_t ap[8], bp[4];
            lds_pair(baseA + kk * 1024 +  0, ap[0], ap[1]);
            lds_pair(baseA + kk * 1024 + 16, ap[2], ap[3]);
            lds_pair(baseA + kk * 1024 + 32, ap[4], ap[5]);
            lds_pair(baseA + kk * 1024 + 48, ap[6], ap[7]);
            lds_pair(baseB + kk * 512 +   0, bp[0], bp[1]);
            lds_pair(baseB + kk * 512 + 256, bp[2], bp[3]);
            #pragma unroll
            for (int i = 0; i < 8; ++i)
                #pragma unroll
                for (int j = 0; j < 4; ++j)
                    acc[i][j] = ffma2(ap[i], bp[j], acc[i][j]);
        }

        if (more) {
            const int nb = (t + 1) & 1;
            float av[8] = {a0.x, a0.y, a0.z, a0.w, a1.x, a1.y, a1.z, a1.w};
            #pragma unroll
            for (int i = 0; i < 8; ++i)
                *(float2*)&As2[nb][ac + i][2 * ar] = make_float2(av[i], av[i]);
            CP_WAIT0();
            __syncthreads();
        }
    }

    // ---- write chunk partial: columns bn0+4tx.. and bn0+64+4tx..
    float* __restrict__ P = g_part[blockIdx.z];
    #pragma unroll
    for (int i = 0; i < 8; ++i) {
        float o[8];
        unpack2(acc[i][0], o[0], o[1]);
        unpack2(acc[i][1], o[2], o[3]);
        unpack2(acc[i][2], o[4], o[5]);
        unpack2(acc[i][3], o[6], o[7]);
        const size_t idx = (size_t)(bm0 + rm + i) * Dd + (bn0 + 4 * tx);
        *(float4*)&P[idx]      = make_float4(o[0], o[1], o[2], o[3]);
        *(float4*)&P[idx + 64] = make_float4(o[4], o[5], o[6], o[7]);
    }

    // ---- grid-wide barrier (all 256 CTAs co-resident: 2/SM x 148 SMs)
    __threadfence();
    __syncthreads();                    // all threads' partial stores issued
    if (tid == 0) {
        int p0 = *(volatile int*)&g_bar_phase;
        int old = atomicAdd(&g_bar_cnt, 1);
        if (old == GRID_CTAS - 1) {
            g_bar_cnt = 0;              // reset for next stage (stream-ordered)
            __threadfence();
            atomicAdd(&g_bar_phase, 1);
        } else {
            while (*(volatile int*)&g_bar_phase == p0) { }
        }
    }
    __syncthreads();
    __threadfence();                    // acquire all CTAs' partials

    // ---- distributed reduce + LIF epilogue: this CTA handles 1/256 of BD.
    // Identical math/order to the standalone reduce kernel.
    const int cta = blockIdx.z * (gridDim.x * gridDim.y)
                  + blockIdx.y * gridDim.x + blockIdx.x;
    float* __restrict__ u_out = g_u[layer];
    float* __restrict__ s_out = g_s[layer];
    float* __restrict__ accb  = (layer == 0) ? g_af : g_al;

    #pragma unroll
    for (int blk = 0; blk < 4; ++blk) {
        const int i4 = (cta * 256 + tid) * 16 + blk * 4;
        const int n  = i4 & (Dd - 1);

        float4 q0 = *(const float4*)&g_part[0][i4];
        float4 q1 = *(const float4*)&g_part[1][i4];
        float4 q2 = *(const float4*)&g_part[2][i4];
        float4 q3 = *(const float4*)&g_part[3][i4];
        float4 bb = *(const float4*)&bias[n];

        float4 uo = make_float4(0, 0, 0, 0), x1v = make_float4(0, 0, 0, 0);
        float4 ab = make_float4(0, 0, 0, 0);
        if (ADD_UPREV) uo  = *(const float4*)&u_out[i4];
        if (ADD_X1)    x1v = *(const float4*)&g_x1[i4];
        if (ACCM == 2 || ACCM == 3) ab = *(const float4*)&accb[i4];

        const float* P0 = (const float*)&q0;
        const float* P1 = (const float*)&q1;
        const float* P2 = (const float*)&q2;
        const float* P3 = (const float*)&q3;
        const float* Bb = (const float*)&bb;
        const float* U  = (const float*)&uo;
        const float* X1 = (const float*)&x1v;
        const float* AB = (const float*)&ab;

        float4 un4, sp4, x1w4, ao4, fo4;
        float* UN  = (float*)&un4;
        float* SP  = (float*)&sp4;
        float* X1W = (float*)&x1w4;
        float* AO  = (float*)&ao4;
        float* FO  = (float*)&fo4;

        #pragma unroll
        for (int l = 0; l < 4; ++l) {
            // dot = ((c0 + c1) + c2) + c3  (ascending chunk order)
            float v = __fadd_rn(__fadd_rn(__fadd_rn(P0[l], P1[l]), P2[l]), P3[l]);
            if (ADD_UPREV) v = __fadd_rn(U[l], v);    // u_prev + dot
            v = __fadd_rn(v, Bb[l]);                  // + bias
            if (ADD_X1)    v = __fadd_rn(v, X1[l]);   // + x1
            if (WRITE_RAW) X1W[l] = v;

            float sp = (v >= VTH) ? 1.0f : 0.0f;
            float un = __fmul_rn(__fsub_rn(v, sp), LK);
            UN[l] = un;
            SP[l] = sp;

            if (ACCM == 1) {
                AO[l] = sp;
            } else if (ACCM == 2) {
                AO[l] = __fadd_rn(__fmul_rn(AB[l], LK), sp);
            } else if (ACCM == 3) {
                float a2 = __fadd_rn(__fmul_rn(AB[l], LK), sp);
                FO[l] = __fdiv_rn(a2, WEIGHTED);
            }
        }

        *(float4*)&u_out[i4] = un4;
        *(float4*)&s_out[i4] = sp4;
        if (WRITE_RAW) *(float4*)&g_x1[i4] = x1w4;
        if (ACCM == 1 || ACCM == 2) *(float4*)&accb[i4] = ao4;
        if (ACCM == 3) *(float4*)&finout[i4] = fo4;
    }
}

extern "C" void kernel_launch(void* const* d_in, const int* in_sizes, int n_in,
                              void* d_out, int out_size)
{
    const float* x  = (const float*)d_in[0];   // [B, D]
    const float* Ws = (const float*)d_in[1];   // [L, D, D]
    const float* bs = (const float*)d_in[2];   // [L, D]
    const float* Wx = (const float*)d_in[3];   // [D, D]
    const float* bx = (const float*)d_in[4];   // [D]
    float* out = (float*)d_out;                // [2, B, D] : af then al

    dim3 gg(Dd / 128, Bsz / 128, NCHUNK);      // (16, 4, 4) = 256 CTAs
    dim3 bbk(256);

    // stage 1: x1 = x @ Wx + bx ; store raw x1; u0,s0 = lif(x1); af = s0
    gemm_lif_fused<false, false, true, 1><<<gg, bbk>>>(x, Wx, bx, -1, 0, nullptr);
    // t = 0, layer 1
    gemm_lif_fused<false, false, false, 0><<<gg, bbk>>>(nullptr, Ws + 0 * DD, bs + 0 * Dd, 0, 1, nullptr);
    // t = 0, layer 2 ; al = s2
    gemm_lif_fused<false, false, false, 1><<<gg, bbk>>>(nullptr, Ws + 1 * DD, bs + 1 * Dd, 1, 2, nullptr);

    for (int t = 1; t < TSTEPS; ++t) {
        const bool last = (t == TSTEPS - 1);
        // layer 0: u0 + s2 @ Ws[2] + bs[2] + x1 ; af update
        if (!last)
            gemm_lif_fused<true, true, false, 2><<<gg, bbk>>>(nullptr, Ws + 2 * DD, bs + 2 * Dd, 2, 0, nullptr);
        else
            gemm_lif_fused<true, true, false, 3><<<gg, bbk>>>(nullptr, Ws + 2 * DD, bs + 2 * Dd, 2, 0, out);
        // layer 1: u1 + s0 @ Ws[0] + bs[0]
        gemm_lif_fused<true, false, false, 0><<<gg, bbk>>>(nullptr, Ws + 0 * DD, bs + 0 * Dd, 0, 1, nullptr);
        // layer 2: u2 + s1 @ Ws[1] + bs[1] ; al update
        if (!last)
            gemm_lif_fused<true, false, false, 2><<<gg, bbk>>>(nullptr, Ws + 1 * DD, bs + 1 * Dd, 1, 2, nullptr);
        else
            gemm_lif_fused<true, false, false, 3><<<gg, bbk>>>(nullptr, Ws + 1 * DD, bs + 1 * Dd, 1, 2, out + BD);
    }
}

// round 17
// speedup vs baseline: 1.1234x; 1.1234x over previous
#include <cuda_runtime.h>
#include <cstdint>

// ---------------------------------------------------------------------------
// SNN multi-layer LIF with feedback. B=512, D=2048, L=3, T=16.
// Bitwise-exact fp32, chunk-512 blocked-K accumulation (verified R4/R5).
// Round 16 (rerun; prior attempt hit an infra failure): R12 two-kernel
// structure (best: 5583us) + (1) 3-stage cp.async pipeline for B tiles
// (dynamic smem 56KB, wait_group 1) and (2) wider reduce kernel
// (8 elems/thread, 512 CTAs).
// Per-output-element FMA chain order identical to R4/R5/R11/R12.
// ---------------------------------------------------------------------------

#define Bsz 512
#define Dd  2048
#define NL  3
#define TSTEPS 16
#define DD (Dd * Dd)
#define BD (Bsz * Dd)
#define NCHUNK 4
#define KCHUNK 512

#define A_BUF 16384u                 // 16*256*4 bytes per As2 buffer
#define B_BUF 8192u                  // 16*128*4 bytes per Bs buffer
#define SMEM_DYN (2 * A_BUF + 3 * B_BUF)   // 57344 bytes

__device__ float g_x1[BD];
__device__ float g_u[NL][BD];
__device__ float g_s[NL][BD];
__device__ float g_af[BD];
__device__ float g_al[BD];
__device__ float g_part[NCHUNK][BD];

#define VTH 1.0f
#define LK  0.9f
// (1 - 0.9^16) / (1 - 0.9) rounded to f32
#define WEIGHTED 8.146979811148159f

__device__ __forceinline__ uint64_t ffma2(uint64_t a, uint64_t b, uint64_t c) {
    uint64_t d;
    asm("fma.rn.f32x2 %0, %1, %2, %3;" : "=l"(d) : "l"(a), "l"(b), "l"(c));
    return d;
}
__device__ __forceinline__ void lds_pair(uint32_t addr, uint64_t& p0, uint64_t& p1) {
    asm volatile("ld.shared.v2.b64 {%0, %1}, [%2];" : "=l"(p0), "=l"(p1) : "r"(addr));
}
__device__ __forceinline__ void unpack2(uint64_t p, float& lo, float& hi) {
    asm("mov.b64 {%0, %1}, %2;" : "=f"(lo), "=f"(hi) : "l"(p));
}
__device__ __forceinline__ void cp16(uint32_t s, const void* g) {
    asm volatile("cp.async.ca.shared.global [%0], [%1], 16;" :: "r"(s), "l"(g));
}
#define CP_COMMIT() asm volatile("cp.async.commit_group;")
#define CP_WAIT1()  asm volatile("cp.async.wait_group 1;")
#define CP_WAIT0()  asm volatile("cp.async.wait_group 0;")

// ---------------------------------------------------------------------------
// GEMM chunk kernel: g_part[z] = A[:, z*512:(z+1)*512] @ W[z*512:(z+1)*512, :]
// BM=BN=128, BK=16, 256 threads, 8x8 micro-tile via packed f32x2 FMA.
// A: dup smem, 2 buffers (LDG->reg->dup STS). B: cp.async, 3 buffers.
// Thread n-columns: {4tx..4tx+3} and {64+4tx..64+4tx+3} (conflict-free B).
// ---------------------------------------------------------------------------
__global__ __launch_bounds__(256, 2)
void gemm_chunk_kernel(const float* __restrict__ Aext,
                       const float* __restrict__ W, int a_sel)
{
    extern __shared__ char smem_raw[];
    float* As2f = (float*)smem_raw;     // 2 x [16][256] dup-A buffers
    const uint32_t smem_base = (uint32_t)__cvta_generic_to_shared(smem_raw);
    const uint32_t bs_base   = smem_base + 2 * A_BUF;

    const float* __restrict__ A = (a_sel < 0) ? Aext : g_s[a_sel];

    const int tid = threadIdx.x;
    const int bn0 = blockIdx.x * 128;
    const int bm0 = blockIdx.y * 128;
    const int k0  = blockIdx.z * KCHUNK;

    // A loader: 128 rows x 16 k; 2 float4 per thread
    const int ar = tid >> 1;            // 0..127
    const int ac = (tid & 1) << 3;      // 0 or 8
    // B loader: 16 k-rows x 128 n; 2 x 16B cp.async per thread
    const int wr = tid >> 4;            // 0..15
    const int wc = (tid & 15) << 3;     // 0..120

    const float* __restrict__ Ap = A + (size_t)(bm0 + ar) * Dd + (k0 + ac);
    const float* __restrict__ Wp = W + (size_t)(k0 + wr) * Dd + (bn0 + wc);

    // rotating B-buffer addresses: store side (loader) and read side (consumer)
    const uint32_t stoff = (uint32_t)(wr * 128 + wc) * 4;
    uint32_t st0 = bs_base + 0 * B_BUF + stoff;
    uint32_t st1 = bs_base + 1 * B_BUF + stoff;
    uint32_t st2 = bs_base + 2 * B_BUF + stoff;

    // prime: B0 into buf0, B1 into buf1, A0 dup store
    {
        cp16(st0, Wp);      cp16(st0 + 16, Wp + 4);      CP_COMMIT();
        cp16(st1, Wp + Dd * 16);  cp16(st1 + 16, Wp + Dd * 16 + 4);  CP_COMMIT();
        float4 a0 = *(const float4*)Ap;
        float4 a1 = *(const float4*)(Ap + 4);
        float av[8] = {a0.x, a0.y, a0.z, a0.w, a1.x, a1.y, a1.z, a1.w};
        #pragma unroll
        for (int i = 0; i < 8; ++i) {
            float2 d = make_float2(av[i], av[i]);
            *(float2*)&As2f[(ac + i) * 256 + 2 * ar] = d;
        }
        CP_WAIT1();         // B0 landed (B1 may be in flight)
    }
    __syncthreads();

    const int tx = tid & 15;            // n group
    const int ty = tid >> 4;            // m group
    const int rm = ty << 3;             // 0..120

    const uint32_t sA = smem_base + (uint32_t)(rm * 8);
    uint32_t rd0 = bs_base + 0 * B_BUF + (uint32_t)(tx * 16);
    uint32_t rd1 = rd0 + B_BUF;
    uint32_t rd2 = rd1 + B_BUF;

    uint64_t acc[8][4];
    #pragma unroll
    for (int i = 0; i < 8; ++i)
        #pragma unroll
        for (int j = 0; j < 4; ++j) acc[i][j] = 0ull;

    const int NT = KCHUNK / 16;         // 32 K-tiles
    #pragma unroll 1
    for (int t = 0; t < NT; ++t) {
        const bool more = (t + 1 < NT);

        // prefetch B(t+2) into rotating slot 2; unconditional commit keeps
        // the group-count invariant for wait_group 1.
        if (t + 2 < NT) {
            const float* Wp2 = Wp + (size_t)(t + 2) * 16 * Dd;
            cp16(st2, Wp2);
            cp16(st2 + 16, Wp2 + 4);
        }
        CP_COMMIT();

        float4 a0, a1;
        if (more) {
            const float* Ap2 = Ap + (t + 1) * 16;
            a0 = *(const float4*)Ap2;
            a1 = *(const float4*)(Ap2 + 4);
        }

        const uint32_t baseA = sA + (uint32_t)(t & 1) * A_BUF;
        const uint32_t baseB = rd0;

        #pragma unroll
        for (int kk = 0; kk < 16; ++kk) {
            uint64_t ap[8], bp[4];
            lds_pair(baseA + kk * 1024 +  0, ap[0], ap[1]);
            lds_pair(baseA + kk * 1024 + 16, ap[2], ap[3]);
            lds_pair(baseA + kk * 1024 + 32, ap[4], ap[5]);
            lds_pair(baseA + kk * 1024 + 48, ap[6], ap[7]);
            // bp[0..1]: n = 4tx..4tx+3 ; bp[2..3]: n = 64+4tx..64+4tx+3
            lds_pair(baseB + kk * 512 +   0, bp[0], bp[1]);
            lds_pair(baseB + kk * 512 + 256, bp[2], bp[3]);
            #pragma unroll
            for (int i = 0; i < 8; ++i)
                #pragma unroll
                for (int j = 0; j < 4; ++j)
                    acc[i][j] = ffma2(ap[i], bp[j], acc[i][j]);
        }

        if (more) {
            const int nb = (t + 1) & 1;
            float av[8] = {a0.x, a0.y, a0.z, a0.w, a1.x, a1.y, a1.z, a1.w};
            #pragma unroll
            for (int i = 0; i < 8; ++i) {
                float2 d = make_float2(av[i], av[i]);
                *(float2*)&As2f[nb * 4096 + (ac + i) * 256 + 2 * ar] = d;
            }
            CP_WAIT1();     // B(t+1) landed; only B(t+2)/empty still pending
            __syncthreads();
        }

        // rotate B buffers
        uint32_t ts = st0; st0 = st1; st1 = st2; st2 = ts;
        uint32_t tr = rd0; rd0 = rd1; rd1 = rd2; rd2 = tr;
    }

    // write chunk partial: columns bn0+4tx.. and bn0+64+4tx..
    float* __restrict__ P = g_part[blockIdx.z];
    #pragma unroll
    for (int i = 0; i < 8; ++i) {
        float o[8];
        unpack2(acc[i][0], o[0], o[1]);
        unpack2(acc[i][1], o[2], o[3]);
        unpack2(acc[i][2], o[4], o[5]);
        unpack2(acc[i][3], o[6], o[7]);
        const size_t idx = (size_t)(bm0 + rm + i) * Dd + (bn0 + 4 * tx);
        *(float4*)&P[idx]      = make_float4(o[0], o[1], o[2], o[3]);
        *(float4*)&P[idx + 64] = make_float4(o[4], o[5], o[6], o[7]);
    }
}

// ---------------------------------------------------------------------------
// Reduce + LIF epilogue: dot = ((p0+p1)+p2)+p3 (ascending chunk order), then
// exact epilogue: v = ((u_prev + dot) + bias) + x1, LIF, af/al.
// 8 elements per thread (two float4 groups), 512 CTAs.
// ---------------------------------------------------------------------------
template<bool ADD_UPREV, bool ADD_X1, bool WRITE_RAW, int ACCM>
__global__ __launch_bounds__(256)
void reduce_lif_kernel(const float* __restrict__ bias, int layer,
                       float* __restrict__ finout)
{
    const int base8 = (blockIdx.x * 256 + threadIdx.x) << 3;

    float* __restrict__ u_out = g_u[layer];
    float* __restrict__ s_out = g_s[layer];
    float* __restrict__ accb  = (layer == 0) ? g_af : g_al;

    #pragma unroll
    for (int h = 0; h < 2; ++h) {
        const int i4 = base8 + h * 4;
        const int n  = i4 & (Dd - 1);

        float4 q0 = *(const float4*)&g_part[0][i4];
        float4 q1 = *(const float4*)&g_part[1][i4];
        float4 q2 = *(const float4*)&g_part[2][i4];
        float4 q3 = *(const float4*)&g_part[3][i4];
        float4 bb = *(const float4*)&bias[n];

        float4 uo = make_float4(0, 0, 0, 0), x1v = make_float4(0, 0, 0, 0);
        float4 ab = make_float4(0, 0, 0, 0);
        if (ADD_UPREV) uo  = *(const float4*)&u_out[i4];
        if (ADD_X1)    x1v = *(const float4*)&g_x1[i4];
        if (ACCM == 2 || ACCM == 3) ab = *(const float4*)&accb[i4];

        const float* P0 = (const float*)&q0;
        const float* P1 = (const float*)&q1;
        const float* P2 = (const float*)&q2;
        const float* P3 = (const float*)&q3;
        const float* Bb = (const float*)&bb;
        const float* U  = (const float*)&uo;
        const float* X1 = (const float*)&x1v;
        const float* AB = (const float*)&ab;

        float4 un4, sp4, x1w4, ao4, fo4;
        float* UN  = (float*)&un4;
        float* SP  = (float*)&sp4;
        float* X1W = (float*)&x1w4;
        float* AO  = (float*)&ao4;
        float* FO  = (float*)&fo4;

        #pragma unroll
        for (int l = 0; l < 4; ++l) {
            // dot = ((c0 + c1) + c2) + c3  (ascending chunk order)
            float v = __fadd_rn(__fadd_rn(__fadd_rn(P0[l], P1[l]), P2[l]), P3[l]);
            if (ADD_UPREV) v = __fadd_rn(U[l], v);    // u_prev + dot
            v = __fadd_rn(v, Bb[l]);                  // + bias
            if (ADD_X1)    v = __fadd_rn(v, X1[l]);   // + x1
            if (WRITE_RAW) X1W[l] = v;

            float sp = (v >= VTH) ? 1.0f : 0.0f;
            float un = __fmul_rn(__fsub_rn(v, sp), LK);
            UN[l] = un;
            SP[l] = sp;

            if (ACCM == 1) {
                AO[l] = sp;
            } else if (ACCM == 2) {
                AO[l] = __fadd_rn(__fmul_rn(AB[l], LK), sp);
            } else if (ACCM == 3) {
                float a2 = __fadd_rn(__fmul_rn(AB[l], LK), sp);
                FO[l] = __fdiv_rn(a2, WEIGHTED);
            }
        }

        *(float4*)&u_out[i4] = un4;
        *(float4*)&s_out[i4] = sp4;
        if (WRITE_RAW) *(float4*)&g_x1[i4] = x1w4;
        if (ACCM == 1 || ACCM == 2) *(float4*)&accb[i4] = ao4;
        if (ACCM == 3) *(float4*)&finout[i4] = fo4;
    }
}

extern "C" void kernel_launch(void* const* d_in, const int* in_sizes, int n_in,
                              void* d_out, int out_size)
{
    const float* x  = (const float*)d_in[0];   // [B, D]
    const float* Ws = (const float*)d_in[1];   // [L, D, D]
    const float* bs = (const float*)d_in[2];   // [L, D]
    const float* Wx = (const float*)d_in[3];   // [D, D]
    const float* bx = (const float*)d_in[4];   // [D]
    float* out = (float*)d_out;                // [2, B, D] : af then al

    // allow 56KB dynamic smem (idempotent; host-side, not a stream op)
    cudaFuncSetAttribute(gemm_chunk_kernel,
                         cudaFuncAttributeMaxDynamicSharedMemorySize, SMEM_DYN);

    dim3 gg(Dd / 128, Bsz / 128, NCHUNK);      // (16, 4, 4) = 256 CTAs
    dim3 bbk(256);
    dim3 gr(BD / 2048);                        // 512 blocks
    dim3 br(256);

    // stage 1: x1 = x @ Wx + bx ; store raw x1; u0,s0 = lif(x1); af = s0
    gemm_chunk_kernel<<<gg, bbk, SMEM_DYN>>>(x, Wx, -1);
    reduce_lif_kernel<false, false, true, 1><<<gr, br>>>(bx, 0, nullptr);
    // t = 0, layer 1
    gemm_chunk_kernel<<<gg, bbk, SMEM_DYN>>>(nullptr, Ws + 0 * DD, 0);
    reduce_lif_kernel<false, false, false, 0><<<gr, br>>>(bs + 0 * Dd, 1, nullptr);
    // t = 0, layer 2 ; al = s2
    gemm_chunk_kernel<<<gg, bbk, SMEM_DYN>>>(nullptr, Ws + 1 * DD, 1);
    reduce_lif_kernel<false, false, false, 1><<<gr, br>>>(bs + 1 * Dd, 2, nullptr);

    for (int t = 1; t < TSTEPS; ++t) {
        const bool last = (t == TSTEPS - 1);
        // layer 0: u0 + s2 @ Ws[2] + bs[2] + x1 ; af update
        gemm_chunk_kernel<<<gg, bbk, SMEM_DYN>>>(nullptr, Ws + 2 * DD, 2);
        if (!last)
            reduce_lif_kernel<true, true, false, 2><<<gr, br>>>(bs + 2 * Dd, 0, nullptr);
        else
            reduce_lif_kernel<true, true, false, 3><<<gr, br>>>(bs + 2 * Dd, 0, out);
        // layer 1: u1 + s0 @ Ws[0] + bs[0]
        gemm_chunk_kernel<<<gg, bbk, SMEM_DYN>>>(nullptr, Ws + 0 * DD, 0);
        reduce_lif_kernel<true, false, false, 0><<<gr, br>>>(bs + 0 * Dd, 1, nullptr);
        // layer 2: u2 + s1 @ Ws[1] + bs[1] ; al update
        gemm_chunk_kernel<<<gg, bbk, SMEM_DYN>>>(nullptr, Ws + 1 * DD, 1);
        if (!last)
            reduce_lif_kernel<true, false, false, 2><<<gr, br>>>(bs + 1 * Dd, 2, nullptr);
        else
            reduce_lif_kernel<true, false, false, 3><<<gr, br>>>(bs + 1 * Dd, 2, out + BD);
    }
}